// round 1
// baseline (speedup 1.0000x reference)
#include <cuda_runtime.h>
#include <math.h>

#define B_  32
#define TQ_ 1024
#define TK_ 1024
#define D_  64

// 32*1024*1024 fp32 scores scratch = 134 MB (static device bss; no runtime alloc)
static __device__ float g_S[(size_t)B_ * TQ_ * TK_];

// ---------------------------------------------------------------------------
// Kernel A: content scores  S[b,q,k] = sum_d Q[b,q,d] * K[b,k,d]   (unscaled)
// grid (TK/128, TQ/128, B), 256 threads, 128x128 tile, 8x8 microtile
// ---------------------------------------------------------------------------
extern "C" __global__ void __launch_bounds__(256)
qk_kernel(const float* __restrict__ Q, const float* __restrict__ K)
{
    const int b  = blockIdx.z;
    const int qt = blockIdx.y * 128;
    const int kt = blockIdx.x * 128;
    const float* Qb = Q + (size_t)b * TQ_ * D_;
    const float* Kb = K + (size_t)b * TK_ * D_;
    float* Sb = g_S + (size_t)b * TQ_ * TK_;

    __shared__ float Qs[32][132];   // [d][m], padded
    __shared__ float Ks[32][132];   // [d][n], padded

    const int tid = threadIdx.x;
    const int ty  = tid >> 4;       // 0..15
    const int tx  = tid & 15;       // 0..15

    float acc[8][8];
#pragma unroll
    for (int i = 0; i < 8; i++)
#pragma unroll
        for (int j = 0; j < 8; j++) acc[i][j] = 0.f;

    for (int k0 = 0; k0 < D_; k0 += 32) {
#pragma unroll
        for (int i = 0; i < 4; i++) {
            int idx = tid + i * 256;        // float4 index over 128x32 tile
            int row = idx >> 3;             // 8 float4 per row
            int dc  = (idx & 7) * 4;
            float4 v = *(const float4*)(Qb + (size_t)(qt + row) * D_ + k0 + dc);
            Qs[dc + 0][row] = v.x; Qs[dc + 1][row] = v.y;
            Qs[dc + 2][row] = v.z; Qs[dc + 3][row] = v.w;
            float4 w = *(const float4*)(Kb + (size_t)(kt + row) * D_ + k0 + dc);
            Ks[dc + 0][row] = w.x; Ks[dc + 1][row] = w.y;
            Ks[dc + 2][row] = w.z; Ks[dc + 3][row] = w.w;
        }
        __syncthreads();
#pragma unroll 4
        for (int kk = 0; kk < 32; kk++) {
            float4 a0 = *(const float4*)&Qs[kk][ty * 8];
            float4 a1 = *(const float4*)&Qs[kk][ty * 8 + 4];
            float4 b0 = *(const float4*)&Ks[kk][tx * 8];
            float4 b1 = *(const float4*)&Ks[kk][tx * 8 + 4];
            float av[8] = {a0.x, a0.y, a0.z, a0.w, a1.x, a1.y, a1.z, a1.w};
            float bv[8] = {b0.x, b0.y, b0.z, b0.w, b1.x, b1.y, b1.z, b1.w};
#pragma unroll
            for (int i = 0; i < 8; i++)
#pragma unroll
                for (int j = 0; j < 8; j++)
                    acc[i][j] += av[i] * bv[j];
        }
        __syncthreads();
    }

#pragma unroll
    for (int i = 0; i < 8; i++) {
        float* dst = Sb + (size_t)(qt + ty * 8 + i) * TK_ + kt + tx * 8;
        *(float4*)(dst)     = make_float4(acc[i][0], acc[i][1], acc[i][2], acc[i][3]);
        *(float4*)(dst + 4) = make_float4(acc[i][4], acc[i][5], acc[i][6], acc[i][7]);
    }
}

// ---------------------------------------------------------------------------
// Kernel B: S[b,q,k] = mask( (S + sum_d Q[b,q,d]*pos_k[q,k,d]) / 8 )
// grid (TK/128, TQ), 256 threads. pos_k read exactly once.
// thread: kg = tid&7 (k = kg + 8j, j<16), b = tid>>3
// ---------------------------------------------------------------------------
extern "C" __global__ void __launch_bounds__(256, 2)
posk_kernel(const float* __restrict__ Q, const float* __restrict__ PK,
            const int* __restrict__ VL)
{
    const int q  = blockIdx.y;
    const int kt = blockIdx.x * 128;

    __shared__ float Ps[128][68];   // pos_k chunk, natural [k][d], padded
    __shared__ float Qs[B_][D_];    // Q[:,q,:]
    __shared__ int   vls[B_];

    const int tid = threadIdx.x;

    const float* PKq = PK + ((size_t)q * TK_ + kt) * D_;
#pragma unroll
    for (int i = 0; i < 8; i++) {
        int idx = tid + i * 256;        // 2048 float4 over 128x64
        int k  = idx >> 4;
        int dc = (idx & 15) * 4;
        *(float4*)&Ps[k][dc] = *(const float4*)(PKq + (size_t)k * D_ + dc);
    }
#pragma unroll
    for (int i = 0; i < 2; i++) {
        int idx = tid + i * 256;        // 512 float4 over 32x64
        int bb = idx >> 4;
        int dc = (idx & 15) * 4;
        *(float4*)&Qs[bb][dc] = *(const float4*)(Q + ((size_t)bb * TQ_ + q) * D_ + dc);
    }
    if (tid < B_) vls[tid] = VL[tid];
    __syncthreads();

    const int kg = tid & 7;
    const int b  = tid >> 3;

    float qreg[64];
#pragma unroll
    for (int i = 0; i < 16; i++) {
        float4 v = *(const float4*)&Qs[b][i * 4];
        qreg[i * 4 + 0] = v.x; qreg[i * 4 + 1] = v.y;
        qreg[i * 4 + 2] = v.z; qreg[i * 4 + 3] = v.w;
    }

    float acc[16];
#pragma unroll 2
    for (int j = 0; j < 16; j++) {
        const int k = kg + j * 8;
        float a0 = 0.f, a1 = 0.f, a2 = 0.f, a3 = 0.f;
#pragma unroll
        for (int dc = 0; dc < 64; dc += 16) {
            float4 p0 = *(const float4*)&Ps[k][dc];
            float4 p1 = *(const float4*)&Ps[k][dc + 4];
            float4 p2 = *(const float4*)&Ps[k][dc + 8];
            float4 p3 = *(const float4*)&Ps[k][dc + 12];
            a0 += qreg[dc +  0] * p0.x + qreg[dc +  1] * p0.y + qreg[dc +  2] * p0.z + qreg[dc +  3] * p0.w;
            a1 += qreg[dc +  4] * p1.x + qreg[dc +  5] * p1.y + qreg[dc +  6] * p1.z + qreg[dc +  7] * p1.w;
            a2 += qreg[dc +  8] * p2.x + qreg[dc +  9] * p2.y + qreg[dc + 10] * p2.z + qreg[dc + 11] * p2.w;
            a3 += qreg[dc + 12] * p3.x + qreg[dc + 13] * p3.y + qreg[dc + 14] * p3.z + qreg[dc + 15] * p3.w;
        }
        acc[j] = (a0 + a1) + (a2 + a3);
    }

    const int vl = vls[b];
    float* Srow = g_S + ((size_t)b * TQ_ + q) * TK_ + kt;
#pragma unroll
    for (int j = 0; j < 16; j++) {
        int k = kg + j * 8;
        float s = Srow[k];
        Srow[k] = (kt + k < vl) ? (s + acc[j]) * 0.125f : -1e6f;
    }
}

// ---------------------------------------------------------------------------
// Kernel C: row softmax over k (1024). grid (TQ, B), 256 threads, 4 elem/thr.
// ---------------------------------------------------------------------------
extern "C" __global__ void __launch_bounds__(256)
softmax_kernel()
{
    const int q = blockIdx.x;
    const int b = blockIdx.y;
    float* row = g_S + ((size_t)b * TQ_ + q) * TK_;
    const int tid = threadIdx.x;

    float4 v = *(float4*)&row[tid * 4];
    float m = fmaxf(fmaxf(v.x, v.y), fmaxf(v.z, v.w));
#pragma unroll
    for (int o = 16; o > 0; o >>= 1) m = fmaxf(m, __shfl_xor_sync(0xffffffffu, m, o));

    __shared__ float red[8];
    if ((tid & 31) == 0) red[tid >> 5] = m;
    __syncthreads();
    float M = red[0];
#pragma unroll
    for (int i = 1; i < 8; i++) M = fmaxf(M, red[i]);

    float e0 = __expf(v.x - M);
    float e1 = __expf(v.y - M);
    float e2 = __expf(v.z - M);
    float e3 = __expf(v.w - M);
    float s = (e0 + e1) + (e2 + e3);
#pragma unroll
    for (int o = 16; o > 0; o >>= 1) s += __shfl_xor_sync(0xffffffffu, s, o);
    __syncthreads();
    if ((tid & 31) == 0) red[tid >> 5] = s;
    __syncthreads();
    float tot = 0.f;
#pragma unroll
    for (int i = 0; i < 8; i++) tot += red[i];
    float inv = 1.0f / tot;
    *(float4*)&row[tid * 4] = make_float4(e0 * inv, e1 * inv, e2 * inv, e3 * inv);
}

// ---------------------------------------------------------------------------
// Kernel D1: O[b,q,d] = sum_k P[b,q,k] * V[b,k,d]   (overwrite)
// grid (TQ/128, B), 256 threads. thread: dg = tid&7, qrow = tid>>3, 4 q's.
// ---------------------------------------------------------------------------
extern "C" __global__ void __launch_bounds__(256)
pv_kernel(const float* __restrict__ V, float* __restrict__ Out)
{
    const int b  = blockIdx.y;
    const int qt = blockIdx.x * 128;
    const float* Vb = V + (size_t)b * TK_ * D_;
    const float* Sb = g_S + (size_t)b * TQ_ * TK_;

    __shared__ float Pm[128][36];   // P chunk [q][k32], padded
    __shared__ float Vs[32][68];    // V chunk [k][d],  padded

    const int tid  = threadIdx.x;
    const int dg   = tid & 7;       // 8 d-groups of 8
    const int qrow = tid >> 3;      // 0..31

    float acc[4][8];
#pragma unroll
    for (int i = 0; i < 4; i++)
#pragma unroll
        for (int j = 0; j < 8; j++) acc[i][j] = 0.f;

    for (int kt = 0; kt < TK_; kt += 32) {
#pragma unroll
        for (int i = 0; i < 4; i++) {
            int idx = tid + i * 256;    // 1024 float4 over 128x32
            int r  = idx >> 3;
            int kc = (idx & 7) * 4;
            *(float4*)&Pm[r][kc] = *(const float4*)(Sb + (size_t)(qt + r) * TK_ + kt + kc);
        }
#pragma unroll
        for (int i = 0; i < 2; i++) {
            int idx = tid + i * 256;    // 512 float4 over 32x64
            int r  = idx >> 4;
            int dc = (idx & 15) * 4;
            *(float4*)&Vs[r][dc] = *(const float4*)(Vb + (size_t)(kt + r) * D_ + dc);
        }
        __syncthreads();
#pragma unroll 4
        for (int k = 0; k < 32; k++) {
            float4 v0 = *(const float4*)&Vs[k][dg * 8];
            float4 v1 = *(const float4*)&Vs[k][dg * 8 + 4];
#pragma unroll
            for (int i = 0; i < 4; i++) {
                float p = Pm[qrow + 32 * i][k];
                acc[i][0] += p * v0.x; acc[i][1] += p * v0.y;
                acc[i][2] += p * v0.z; acc[i][3] += p * v0.w;
                acc[i][4] += p * v1.x; acc[i][5] += p * v1.y;
                acc[i][6] += p * v1.z; acc[i][7] += p * v1.w;
            }
        }
        __syncthreads();
    }

#pragma unroll
    for (int i = 0; i < 4; i++) {
        float* dst = Out + ((size_t)b * TQ_ + qt + qrow + 32 * i) * D_ + dg * 8;
        *(float4*)(dst)     = make_float4(acc[i][0], acc[i][1], acc[i][2], acc[i][3]);
        *(float4*)(dst + 4) = make_float4(acc[i][4], acc[i][5], acc[i][6], acc[i][7]);
    }
}

// ---------------------------------------------------------------------------
// Kernel D2: O[b,q,d] += sum_k P[b,q,k] * pos_v[q,k,d]
// grid (TQ), 256 threads. pos_v read exactly once. dg = tid&7, b = tid>>3.
// ---------------------------------------------------------------------------
extern "C" __global__ void __launch_bounds__(256)
posv_kernel(const float* __restrict__ PV, float* __restrict__ Out)
{
    const int q = blockIdx.x;

    __shared__ float PVs[64][68];   // pos_v chunk [k][d], padded
    __shared__ float Pm[B_][68];    // P chunk [b][k64], padded

    const int tid = threadIdx.x;
    const int dg  = tid & 7;
    const int b   = tid >> 3;

    float acc[8];
#pragma unroll
    for (int j = 0; j < 8; j++) acc[j] = 0.f;

    for (int kt = 0; kt < TK_; kt += 64) {
        const float* PVq = PV + ((size_t)q * TK_ + kt) * D_;
#pragma unroll
        for (int i = 0; i < 4; i++) {
            int idx = tid + i * 256;    // 1024 float4 over 64x64
            int k  = idx >> 4;
            int dc = (idx & 15) * 4;
            *(float4*)&PVs[k][dc] = *(const float4*)(PVq + (size_t)k * D_ + dc);
        }
#pragma unroll
        for (int i = 0; i < 2; i++) {
            int idx = tid + i * 256;    // 512 float4 over 32x64
            int bb = idx >> 4;
            int kc = (idx & 15) * 4;
            *(float4*)&Pm[bb][kc] =
                *(const float4*)(g_S + ((size_t)bb * TQ_ + q) * TK_ + kt + kc);
        }
        __syncthreads();
#pragma unroll 4
        for (int k = 0; k < 64; k++) {
            float p = Pm[b][k];
            float4 v0 = *(const float4*)&PVs[k][dg * 8];
            float4 v1 = *(const float4*)&PVs[k][dg * 8 + 4];
            acc[0] += p * v0.x; acc[1] += p * v0.y;
            acc[2] += p * v0.z; acc[3] += p * v0.w;
            acc[4] += p * v1.x; acc[5] += p * v1.y;
            acc[6] += p * v1.z; acc[7] += p * v1.w;
        }
        __syncthreads();
    }

    float* dst = Out + ((size_t)b * TQ_ + q) * D_ + dg * 8;
    float4 o0 = *(float4*)(dst);
    float4 o1 = *(float4*)(dst + 4);
    o0.x += acc[0]; o0.y += acc[1]; o0.z += acc[2]; o0.w += acc[3];
    o1.x += acc[4]; o1.y += acc[5]; o1.z += acc[6]; o1.w += acc[7];
    *(float4*)(dst)     = o0;
    *(float4*)(dst + 4) = o1;
}

// ---------------------------------------------------------------------------
extern "C" void kernel_launch(void* const* d_in, const int* in_sizes, int n_in,
                              void* d_out, int out_size)
{
    const float* Q  = (const float*)d_in[0];
    const float* K  = (const float*)d_in[1];
    const float* V  = (const float*)d_in[2];
    const float* PK = (const float*)d_in[3];
    const float* PV = (const float*)d_in[4];
    const int*   VL = (const int*)d_in[5];
    float* Out = (float*)d_out;

    qk_kernel<<<dim3(TK_ / 128, TQ_ / 128, B_), 256>>>(Q, K);
    posk_kernel<<<dim3(TK_ / 128, TQ_), 256>>>(Q, PK, VL);
    softmax_kernel<<<dim3(TQ_, B_), 256>>>();
    pv_kernel<<<dim3(TQ_ / 128, B_), 256>>>(V, Out);
    posv_kernel<<<TQ_, 256>>>(PV, Out);
}